// round 12
// baseline (speedup 1.0000x reference)
#include <cuda_runtime.h>
#include <cuda_bf16.h>
#include <cstdint>

#define NMAX   50000
#define DIMC   256
#define KNBR   16
#define QSCALE 0.17677669529663689f   // 1/sqrt(32)

// ---------------- device scratch (no allocations allowed) -------------------
__device__ __nv_bfloat16 f_hi[(size_t)NMAX * DIMC];
__device__ __nv_bfloat16 f_lo[(size_t)NMAX * DIMC];
__device__ __nv_bfloat16 w_hi[768 * 256];
__device__ __nv_bfloat16 w_lo[768 * 256];
__device__ __nv_bfloat16 pw_hi[256 * 256];
__device__ __nv_bfloat16 pw_lo[256 * 256];
__device__ float g_q[(size_t)NMAX * DIMC];
__device__ float g_k[(size_t)NMAX * DIMC];
__device__ float g_v[(size_t)NMAX * DIMC];
__device__ __nv_bfloat16 x_hi[(size_t)NMAX * DIMC];
__device__ __nv_bfloat16 x_lo[(size_t)NMAX * DIMC];

// ---------------- helpers ---------------------------------------------------
__device__ __forceinline__ uint32_t smem_u32(const void* p) {
    uint32_t a;
    asm("{ .reg .u64 t; cvta.to.shared.u64 t, %1; cvt.u32.u64 %0, t; }" : "=r"(a) : "l"(p));
    return a;
}
__device__ __forceinline__ void cp_async16(uint32_t saddr, const void* gaddr, int srcb) {
    asm volatile("cp.async.cg.shared.global [%0], [%1], 16, %2;"
                 :: "r"(saddr), "l"(gaddr), "r"(srcb));
}
__device__ __forceinline__ void cp_commit() { asm volatile("cp.async.commit_group;" ::: "memory"); }
__device__ __forceinline__ void cp_wait1()  { asm volatile("cp.async.wait_group 1;" ::: "memory"); }
__device__ __forceinline__ void cp_wait0()  { asm volatile("cp.async.wait_group 0;" ::: "memory"); }

// fp32 -> (bf16 hi, bf16 lo) split.  which: 0=feats, 1=qkv_w, 2=proj_w
__global__ void cvt_hilo(const float* __restrict__ src, int which, int n) {
    int i = blockIdx.x * blockDim.x + threadIdx.x;
    if (i >= n) return;
    __nv_bfloat16* hi = (which == 0) ? f_hi : (which == 1) ? w_hi : pw_hi;
    __nv_bfloat16* lo = (which == 0) ? f_lo : (which == 1) ? w_lo : pw_lo;
    float x = src[i];
    __nv_bfloat16 h = __float2bfloat16(x);
    hi[i] = h;
    lo[i] = __float2bfloat16(x - __bfloat162float(h));
}

// ---------------------------------------------------------------------------
// Fused split-bf16 GEMM on mma.sync, cp.async double-buffered, 2 CTAs/SM.
// C = A@W^T + bias via AhBh + AhBl + AlBh (fp32 acc).
// Block tile 128x128, 8 warps (4x2), warp tile 32x64, K chunks of 32 elts.
// SMEM row (128B) = hi(64B) | lo(64B) of one matrix row's 32-elt chunk;
// SW128 xor swizzle; stage = A 16KB + B 16KB = 32KB, 2 stages = 64KB.
// SPLIT=1: A=f_hi/lo, W=w_hi/lo (768 cols) -> g_q(*QSCALE)/g_k/g_v
// SPLIT=0: A=x_hi/lo, W=pw_hi/lo (256 cols) -> Cout
// ---------------------------------------------------------------------------
template <int SPLIT>
__global__ void __launch_bounds__(256, 2) gemm_mma(const float* __restrict__ bias,
                                                   float* __restrict__ Cout, int M)
{
    extern __shared__ __align__(1024) char smem[];

    const int t    = threadIdx.x;
    const int lane = t & 31;
    const int w    = t >> 5;
    const int wm   = w & 3;            // 4 warps over M (32 rows)
    const int wn   = w >> 2;           // 2 warps over N (64 cols)
    const int m0   = blockIdx.x * 128;
    const int n0   = blockIdx.y * 128;
    const uint32_t sb = smem_u32(smem);

    const __nv_bfloat16* Ah = SPLIT ? f_hi : x_hi;
    const __nv_bfloat16* Al = SPLIT ? f_lo : x_lo;
    const __nv_bfloat16* Bh = SPLIT ? w_hi : pw_hi;
    const __nv_bfloat16* Bl = SPLIT ? w_lo : pw_lo;

    // gmem->smem: thread covers row = t>>1, part = t&1 (0: hi half, 1: lo half)
    const int ldRow  = t >> 1;
    const int part   = t & 1;
    const bool a_ok  = (m0 + ldRow) < M;
    const int aRow   = a_ok ? (m0 + ldRow) : 0;
    const int aBytes = a_ok ? 16 : 0;
    const uint32_t ldXor = (uint32_t)((ldRow & 7) * 16);

    const __nv_bfloat16* Asrc = part ? Al : Ah;
    const __nv_bfloat16* Bsrc = part ? Bl : Bh;

    auto prefetch = [&](int c) {   // c in [0,8): 32 k-elements per chunk
        const uint32_t stb = sb + (uint32_t)(c & 1) * 32768u;
        const char* gA = (const char*)(Asrc + (size_t)aRow * 256 + c * 32);
        const char* gB = (const char*)(Bsrc + (size_t)(n0 + ldRow) * 256 + c * 32);
#pragma unroll
        for (int j = 0; j < 4; j++) {
            uint32_t so = (uint32_t)(ldRow * 128) + ((uint32_t)(part * 64 + j * 16) ^ ldXor);
            cp_async16(stb + so,          gA + j * 16, aBytes);
            cp_async16(stb + 16384 + so,  gB + j * 16, 16);
        }
    };

    // ldmatrix lane address components
    const int aRowIn = lane & 15;
    const int aKbAdd = (lane >> 4) * 16;
    const int bNIn   = (lane & 7) + ((lane >> 4) << 3);
    const int bKbAdd = ((lane >> 3) & 1) * 16;

    float acc[2][8][4];
#pragma unroll
    for (int f = 0; f < 2; f++)
#pragma unroll
        for (int g = 0; g < 8; g++)
#pragma unroll
            for (int e = 0; e < 4; e++) acc[f][g][e] = 0.f;

    prefetch(0);
    cp_commit();

#pragma unroll 1
    for (int c = 0; c < 8; c++) {
        if (c < 7) { prefetch(c + 1); cp_commit(); cp_wait1(); }
        else       { cp_wait0(); }
        __syncthreads();

        const uint32_t stb = sb + (uint32_t)(c & 1) * 32768u;
        const uint32_t bA = stb, bB = stb + 16384;

#pragma unroll
        for (int ks = 0; ks < 2; ks++) {
            const uint32_t kByte = (uint32_t)(ks * 32);

            uint32_t afH[2][4], afL[2][4];
#pragma unroll
            for (int f = 0; f < 2; f++) {
                int row = wm * 32 + f * 16 + aRowIn;
                uint32_t swz = (uint32_t)((row & 7) * 16);
                uint32_t offH = (uint32_t)(row * 128) + ((kByte + (uint32_t)aKbAdd) ^ swz);
                uint32_t offL = (uint32_t)(row * 128) + ((kByte + (uint32_t)aKbAdd + 64u) ^ swz);
                asm volatile("ldmatrix.sync.aligned.m8n8.x4.shared.b16 {%0,%1,%2,%3}, [%4];"
                             : "=r"(afH[f][0]), "=r"(afH[f][1]), "=r"(afH[f][2]), "=r"(afH[f][3])
                             : "r"(bA + offH));
                asm volatile("ldmatrix.sync.aligned.m8n8.x4.shared.b16 {%0,%1,%2,%3}, [%4];"
                             : "=r"(afL[f][0]), "=r"(afL[f][1]), "=r"(afL[f][2]), "=r"(afL[f][3])
                             : "r"(bA + offL));
            }

#define MMA_BF16(ACC, AF, B0, B1)                                              \
            asm volatile(                                                      \
                "mma.sync.aligned.m16n8k16.row.col.f32.bf16.bf16.f32 "        \
                "{%0,%1,%2,%3}, {%4,%5,%6,%7}, {%8,%9}, {%0,%1,%2,%3};"       \
                : "+f"((ACC)[0]), "+f"((ACC)[1]), "+f"((ACC)[2]), "+f"((ACC)[3]) \
                : "r"((AF)[0]), "r"((AF)[1]), "r"((AF)[2]), "r"((AF)[3]),      \
                  "r"(B0), "r"(B1))

#pragma unroll
            for (int g2 = 0; g2 < 4; g2++) {
                int nb = wn * 64 + g2 * 16 + bNIn;
                uint32_t swz = (uint32_t)((nb & 7) * 16);
                uint32_t offH = (uint32_t)(nb * 128) + ((kByte + (uint32_t)bKbAdd) ^ swz);
                uint32_t offL = (uint32_t)(nb * 128) + ((kByte + (uint32_t)bKbAdd + 64u) ^ swz);
                uint32_t bh[4], bl[4];
                asm volatile("ldmatrix.sync.aligned.m8n8.x4.shared.b16 {%0,%1,%2,%3}, [%4];"
                             : "=r"(bh[0]), "=r"(bh[1]), "=r"(bh[2]), "=r"(bh[3])
                             : "r"(bB + offH));
                asm volatile("ldmatrix.sync.aligned.m8n8.x4.shared.b16 {%0,%1,%2,%3}, [%4];"
                             : "=r"(bl[0]), "=r"(bl[1]), "=r"(bl[2]), "=r"(bl[3])
                             : "r"(bB + offL));
#pragma unroll
                for (int f = 0; f < 2; f++) {
                    MMA_BF16(acc[f][g2 * 2],     afH[f], bh[0], bh[1]);
                    MMA_BF16(acc[f][g2 * 2 + 1], afH[f], bh[2], bh[3]);
                    MMA_BF16(acc[f][g2 * 2],     afH[f], bl[0], bl[1]);
                    MMA_BF16(acc[f][g2 * 2 + 1], afH[f], bl[2], bl[3]);
                    MMA_BF16(acc[f][g2 * 2],     afL[f], bh[0], bh[1]);
                    MMA_BF16(acc[f][g2 * 2 + 1], afL[f], bh[2], bh[3]);
                }
            }
#undef MMA_BF16
        }
        if (c < 7) __syncthreads();
    }

    // ---- epilogue ----
    const int rBase = m0 + wm * 32 + (lane >> 2);
    const int cIn   = (lane & 3) * 2;

    const int sect = SPLIT ? (n0 >> 8) : 0;
    float* dstBase = SPLIT ? ((sect == 0) ? g_q : (sect == 1) ? g_k : g_v) : Cout;
    const float mult = (SPLIT && sect == 0) ? QSCALE : 1.0f;
    const int nLocal = SPLIT ? (n0 & 255) : n0;

#pragma unroll
    for (int f = 0; f < 2; f++) {
#pragma unroll
        for (int g = 0; g < 8; g++) {
            const int colFull = n0 + wn * 64 + g * 8 + cIn;
            const int colOut  = nLocal + wn * 64 + g * 8 + cIn;
            const float b0 = bias[colFull], b1 = bias[colFull + 1];
#pragma unroll
            for (int h = 0; h < 2; h++) {
                const int row = rBase + f * 16 + h * 8;
                if (row < M) {
                    float2 ov;
                    ov.x = (acc[f][g][h * 2 + 0] + b0) * mult;
                    ov.y = (acc[f][g][h * 2 + 1] + b1) * mult;
                    *reinterpret_cast<float2*>(dstBase + (size_t)row * 256 + colOut) = ov;
                }
            }
        }
    }
}

// ---------------------------------------------------------------------------
// Attention: warp per (point, head). No smem, no __syncthreads.
// ---------------------------------------------------------------------------
__global__ void __launch_bounds__(256) attn_kernel(const int* __restrict__ index_1, int M)
{
    const int gw   = (blockIdx.x * 256 + threadIdx.x) >> 5;   // global warp id
    const int i    = gw >> 3;
    const int h    = gw & 7;
    const int lane = threadIdx.x & 31;
    if (i >= M) return;

    int nj = 0;
    if (lane < 16) nj = __ldg(index_1 + i * KNBR + lane);

    const int jj   = lane & 15;
    const int half = lane >> 4;
    const int nbrj = __shfl_sync(0xffffffffu, nj, jj);

    const float4* kr = reinterpret_cast<const float4*>(g_k + (size_t)nbrj * 256 + h * 32 + half * 16);
    const float4* qr = reinterpret_cast<const float4*>(g_q + (size_t)i * 256 + h * 32 + half * 16);
    float dot = 0.f;
#pragma unroll
    for (int d4 = 0; d4 < 4; d4++) {
        float4 kv = kr[d4];
        float4 qv = qr[d4];
        dot += qv.x * kv.x + qv.y * kv.y + qv.z * kv.z + qv.w * kv.w;
    }
    dot += __shfl_xor_sync(0xffffffffu, dot, 16);

    float mx = dot;
#pragma unroll
    for (int o = 8; o > 0; o >>= 1) mx = fmaxf(mx, __shfl_xor_sync(0xffffffffu, mx, o));
    float e = __expf(dot - mx);
    float s = e;
#pragma unroll
    for (int o = 8; o > 0; o >>= 1) s += __shfl_xor_sync(0xffffffffu, s, o);
    const float wgt = e / s;

    const float* vb = g_v + h * 32 + lane;
    float acc = 0.f;
#pragma unroll
    for (int j = 0; j < 16; j++) {
        float wj = __shfl_sync(0xffffffffu, wgt, j);
        int   n  = __shfl_sync(0xffffffffu, nj, j);
        acc += wj * vb[(size_t)n * 256];
    }

    __nv_bfloat16 hv = __float2bfloat16(acc);
    const size_t xo = (size_t)i * 256 + h * 32 + lane;
    x_hi[xo] = hv;
    x_lo[xo] = __float2bfloat16(acc - __bfloat162float(hv));
}

// ---------------------------------------------------------------------------
extern "C" void kernel_launch(void* const* d_in, const int* in_sizes, int n_in,
                              void* d_out, int out_size)
{
    const float* feats   = (const float*)d_in[0];
    const int*   index_1 = (const int*)d_in[3];

    int iw = -1;
    for (int i = 0; i < n_in; i++)
        if (in_sizes[i] == 3 * DIMC * DIMC) { iw = i; break; }
    const float* qkv_w  = (const float*)d_in[iw];
    const float* qkv_b  = (const float*)d_in[iw + 1];
    const float* proj_w = (const float*)d_in[iw + 2];
    const float* proj_b = (const float*)d_in[iw + 3];

    const int M = in_sizes[0] / DIMC;   // 50000

    const int SMEM_BYTES = 65536;       // 2 stages x 32KB
    cudaFuncSetAttribute(gemm_mma<1>, cudaFuncAttributeMaxDynamicSharedMemorySize, SMEM_BYTES);
    cudaFuncSetAttribute(gemm_mma<0>, cudaFuncAttributeMaxDynamicSharedMemorySize, SMEM_BYTES);

    cvt_hilo<<<(M * DIMC + 255) / 256, 256>>>(feats, 0, M * DIMC);
    cvt_hilo<<<(768 * 256 + 255) / 256, 256>>>(qkv_w, 1, 768 * 256);
    cvt_hilo<<<(256 * 256 + 255) / 256, 256>>>(proj_w, 2, 256 * 256);

    dim3 g_qkv((M + 127) / 128, 6);     // 768 output cols
    gemm_mma<1><<<g_qkv, 256, SMEM_BYTES>>>(qkv_b, nullptr, M);

    attn_kernel<<<M, 256>>>(index_1, M);

    dim3 g_proj((M + 127) / 128, 2);    // 256 output cols
    gemm_mma<0><<<g_proj, 256, SMEM_BYTES>>>(proj_b, (float*)d_out, M);
}

// round 13
// speedup vs baseline: 1.0708x; 1.0708x over previous
#include <cuda_runtime.h>
#include <cuda_bf16.h>
#include <cstdint>

#define NMAX   50000
#define DIMC   256
#define KNBR   16
#define QSCALE 0.17677669529663689f   // 1/sqrt(32)

// ---------------- device scratch (no allocations allowed) -------------------
__device__ __nv_bfloat16 f_hi[(size_t)NMAX * DIMC];
__device__ __nv_bfloat16 f_lo[(size_t)NMAX * DIMC];
__device__ __nv_bfloat16 w_hi[768 * 256];
__device__ __nv_bfloat16 w_lo[768 * 256];
__device__ __nv_bfloat16 pw_hi[256 * 256];
__device__ __nv_bfloat16 pw_lo[256 * 256];
__device__ float g_q[(size_t)NMAX * DIMC];
__device__ float g_k[(size_t)NMAX * DIMC];
__device__ float g_v[(size_t)NMAX * DIMC];
__device__ __nv_bfloat16 x_hi[(size_t)NMAX * DIMC];
__device__ __nv_bfloat16 x_lo[(size_t)NMAX * DIMC];

// ---------------- helpers ---------------------------------------------------
__device__ __forceinline__ uint32_t smem_u32(const void* p) {
    uint32_t a;
    asm("{ .reg .u64 t; cvta.to.shared.u64 t, %1; cvt.u32.u64 %0, t; }" : "=r"(a) : "l"(p));
    return a;
}
__device__ __forceinline__ void cp_async16(uint32_t saddr, const void* gaddr, int srcb) {
    asm volatile("cp.async.cg.shared.global [%0], [%1], 16, %2;"
                 :: "r"(saddr), "l"(gaddr), "r"(srcb));
}
__device__ __forceinline__ void cp_commit() { asm volatile("cp.async.commit_group;" ::: "memory"); }
__device__ __forceinline__ void cp_wait1()  { asm volatile("cp.async.wait_group 1;" ::: "memory"); }
__device__ __forceinline__ void cp_wait0()  { asm volatile("cp.async.wait_group 0;" ::: "memory"); }

// fp32 -> (bf16 hi, bf16 lo) split.  which: 0=feats, 1=qkv_w, 2=proj_w
__global__ void cvt_hilo(const float* __restrict__ src, int which, int n) {
    int i = blockIdx.x * blockDim.x + threadIdx.x;
    if (i >= n) return;
    __nv_bfloat16* hi = (which == 0) ? f_hi : (which == 1) ? w_hi : pw_hi;
    __nv_bfloat16* lo = (which == 0) ? f_lo : (which == 1) ? w_lo : pw_lo;
    float x = src[i];
    __nv_bfloat16 h = __float2bfloat16(x);
    hi[i] = h;
    lo[i] = __float2bfloat16(x - __bfloat162float(h));
}

// ---------------------------------------------------------------------------
// Fused split-bf16 GEMM on mma.sync, cp.async double-buffered.
// C = A@W^T + bias via AhBh + AhBl + AlBh (fp32 acc, ~16 mantissa bits).
// Block tile 128x128, 8 warps (4x2), warp tile 32x64, K chunks of 64.
// Stage (64KB): AH@0, AL@16K, BH@32K, BL@48K, rows 128B SW-swizzled.
// MMA issue is PRODUCT-MAJOR: 16 independent accumulators per pass, so
// same-accumulator reuse distance is 16 MMAs (ILP), not 2.
// SPLIT=1: A=f_hi/lo, W=w_hi/lo (768 cols) -> g_q(*QSCALE)/g_k/g_v
// SPLIT=0: A=x_hi/lo, W=pw_hi/lo (256 cols) -> Cout
// ---------------------------------------------------------------------------
template <int SPLIT>
__global__ void __launch_bounds__(256) gemm_mma(const float* __restrict__ bias,
                                                float* __restrict__ Cout, int M)
{
    extern __shared__ __align__(1024) char smem[];

    const int t    = threadIdx.x;
    const int lane = t & 31;
    const int w    = t >> 5;
    const int wm   = w & 3;            // 4 warps over M (32 rows)
    const int wn   = w >> 2;           // 2 warps over N (64 cols)
    const int m0   = blockIdx.x * 128;
    const int n0   = blockIdx.y * 128;
    const uint32_t sb = smem_u32(smem);

    const __nv_bfloat16* Ah = SPLIT ? f_hi : x_hi;
    const __nv_bfloat16* Al = SPLIT ? f_lo : x_lo;
    const __nv_bfloat16* Bh = SPLIT ? w_hi : pw_hi;
    const __nv_bfloat16* Bl = SPLIT ? w_lo : pw_lo;

    // gmem->smem: thread covers row = t>>1, 64B half = t&1 (4 x 16B)
    const int ldRow  = t >> 1;
    const int ldHalf = t & 1;
    const bool a_ok  = (m0 + ldRow) < M;
    const int aRow   = a_ok ? (m0 + ldRow) : 0;
    const int aBytes = a_ok ? 16 : 0;
    const uint32_t ldXor = (uint32_t)((ldRow & 7) * 16);

    auto prefetch = [&](int c) {
        const uint32_t stb = sb + (uint32_t)(c & 1) * 65536u;
        const char* gAh = (const char*)(Ah + (size_t)aRow * 256 + c * 64 + ldHalf * 32);
        const char* gAl = (const char*)(Al + (size_t)aRow * 256 + c * 64 + ldHalf * 32);
        const char* gBh = (const char*)(Bh + (size_t)(n0 + ldRow) * 256 + c * 64 + ldHalf * 32);
        const char* gBl = (const char*)(Bl + (size_t)(n0 + ldRow) * 256 + c * 64 + ldHalf * 32);
#pragma unroll
        for (int j = 0; j < 4; j++) {
            uint32_t so = (uint32_t)(ldRow * 128) + ((uint32_t)(ldHalf * 64 + j * 16) ^ ldXor);
            cp_async16(stb + so,          gAh + j * 16, aBytes);
            cp_async16(stb + 16384 + so,  gAl + j * 16, aBytes);
            cp_async16(stb + 32768 + so,  gBh + j * 16, 16);
            cp_async16(stb + 49152 + so,  gBl + j * 16, 16);
        }
    };

    // ldmatrix lane address components
    const int aRowIn = lane & 15;
    const int aKbAdd = (lane >> 4) * 16;
    const int bNIn   = (lane & 7) + ((lane >> 4) << 3);
    const int bKbAdd = ((lane >> 3) & 1) * 16;

    float acc[2][8][4];
#pragma unroll
    for (int f = 0; f < 2; f++)
#pragma unroll
        for (int g = 0; g < 8; g++)
#pragma unroll
            for (int e = 0; e < 4; e++) acc[f][g][e] = 0.f;

    prefetch(0);
    cp_commit();

#pragma unroll 1
    for (int c = 0; c < 4; c++) {
        if (c < 3) { prefetch(c + 1); cp_commit(); cp_wait1(); }
        else       { cp_wait0(); }
        __syncthreads();

        const uint32_t stb = sb + (uint32_t)(c & 1) * 65536u;
        const uint32_t bAH = stb, bAL = stb + 16384, bBH = stb + 32768, bBL = stb + 49152;

#pragma unroll
        for (int ks = 0; ks < 4; ks++) {
            const uint32_t kByte = (uint32_t)(ks * 32);

            uint32_t afH[2][4], afL[2][4];
#pragma unroll
            for (int f = 0; f < 2; f++) {
                int row = wm * 32 + f * 16 + aRowIn;
                uint32_t kb  = kByte + (uint32_t)aKbAdd;
                uint32_t off = (uint32_t)(row * 128) + (kb ^ (uint32_t)((row & 7) * 16));
                asm volatile("ldmatrix.sync.aligned.m8n8.x4.shared.b16 {%0,%1,%2,%3}, [%4];"
                             : "=r"(afH[f][0]), "=r"(afH[f][1]), "=r"(afH[f][2]), "=r"(afH[f][3])
                             : "r"(bAH + off));
                asm volatile("ldmatrix.sync.aligned.m8n8.x4.shared.b16 {%0,%1,%2,%3}, [%4];"
                             : "=r"(afL[f][0]), "=r"(afL[f][1]), "=r"(afL[f][2]), "=r"(afL[f][3])
                             : "r"(bAL + off));
            }

            uint32_t bfH[4][4], bfL[4][4];
#pragma unroll
            for (int g2 = 0; g2 < 4; g2++) {
                int nb = wn * 64 + g2 * 16 + bNIn;
                uint32_t kb  = kByte + (uint32_t)bKbAdd;
                uint32_t off = (uint32_t)(nb * 128) + (kb ^ (uint32_t)((nb & 7) * 16));
                asm volatile("ldmatrix.sync.aligned.m8n8.x4.shared.b16 {%0,%1,%2,%3}, [%4];"
                             : "=r"(bfH[g2][0]), "=r"(bfH[g2][1]), "=r"(bfH[g2][2]), "=r"(bfH[g2][3])
                             : "r"(bBH + off));
                asm volatile("ldmatrix.sync.aligned.m8n8.x4.shared.b16 {%0,%1,%2,%3}, [%4];"
                             : "=r"(bfL[g2][0]), "=r"(bfL[g2][1]), "=r"(bfL[g2][2]), "=r"(bfL[g2][3])
                             : "r"(bBL + off));
            }

#define MMA_BF16(ACC, AF, B0, B1)                                              \
            asm volatile(                                                      \
                "mma.sync.aligned.m16n8k16.row.col.f32.bf16.bf16.f32 "        \
                "{%0,%1,%2,%3}, {%4,%5,%6,%7}, {%8,%9}, {%0,%1,%2,%3};"       \
                : "+f"((ACC)[0]), "+f"((ACC)[1]), "+f"((ACC)[2]), "+f"((ACC)[3]) \
                : "r"((AF)[0]), "r"((AF)[1]), "r"((AF)[2]), "r"((AF)[3]),      \
                  "r"(B0), "r"(B1))

            // ---- product-major issue: 16 independent accs per pass ----
#pragma unroll
            for (int f = 0; f < 2; f++)
#pragma unroll
                for (int g2 = 0; g2 < 4; g2++) {
                    MMA_BF16(acc[f][g2 * 2],     afH[f], bfH[g2][0], bfH[g2][1]);
                    MMA_BF16(acc[f][g2 * 2 + 1], afH[f], bfH[g2][2], bfH[g2][3]);
                }
#pragma unroll
            for (int f = 0; f < 2; f++)
#pragma unroll
                for (int g2 = 0; g2 < 4; g2++) {
                    MMA_BF16(acc[f][g2 * 2],     afH[f], bfL[g2][0], bfL[g2][1]);
                    MMA_BF16(acc[f][g2 * 2 + 1], afH[f], bfL[g2][2], bfL[g2][3]);
                }
#pragma unroll
            for (int f = 0; f < 2; f++)
#pragma unroll
                for (int g2 = 0; g2 < 4; g2++) {
                    MMA_BF16(acc[f][g2 * 2],     afL[f], bfH[g2][0], bfH[g2][1]);
                    MMA_BF16(acc[f][g2 * 2 + 1], afL[f], bfH[g2][2], bfH[g2][3]);
                }
#undef MMA_BF16
        }
        if (c < 3) __syncthreads();
    }

    // ---- epilogue ----
    const int rBase = m0 + wm * 32 + (lane >> 2);
    const int cIn   = (lane & 3) * 2;

    const int sect = SPLIT ? (n0 >> 8) : 0;
    float* dstBase = SPLIT ? ((sect == 0) ? g_q : (sect == 1) ? g_k : g_v) : Cout;
    const float mult = (SPLIT && sect == 0) ? QSCALE : 1.0f;
    const int nLocal = SPLIT ? (n0 & 255) : n0;

#pragma unroll
    for (int f = 0; f < 2; f++) {
#pragma unroll
        for (int g = 0; g < 8; g++) {
            const int colFull = n0 + wn * 64 + g * 8 + cIn;
            const int colOut  = nLocal + wn * 64 + g * 8 + cIn;
            const float b0 = bias[colFull], b1 = bias[colFull + 1];
#pragma unroll
            for (int h = 0; h < 2; h++) {
                const int row = rBase + f * 16 + h * 8;
                if (row < M) {
                    float2 ov;
                    ov.x = (acc[f][g][h * 2 + 0] + b0) * mult;
                    ov.y = (acc[f][g][h * 2 + 1] + b1) * mult;
                    *reinterpret_cast<float2*>(dstBase + (size_t)row * 256 + colOut) = ov;
                }
            }
        }
    }
}

// ---------------------------------------------------------------------------
// Attention: warp per (point, head). No smem, no __syncthreads.
// Logit phase: lane pair (j, half) reads ADJACENT 16B blocks ((2*d4+half)*16B)
// so each pair fills full 32B L2 sectors (no wasted sector halves).
// ---------------------------------------------------------------------------
__global__ void __launch_bounds__(256) attn_kernel(const int* __restrict__ index_1, int M)
{
    const int gw   = (blockIdx.x * 256 + threadIdx.x) >> 5;   // global warp id
    const int i    = gw >> 3;
    const int h    = gw & 7;
    const int lane = threadIdx.x & 31;
    if (i >= M) return;

    int nj = 0;
    if (lane < 16) nj = __ldg(index_1 + i * KNBR + lane);

    const int jj   = lane & 15;
    const int half = lane >> 4;
    const int nbrj = __shfl_sync(0xffffffffu, nj, jj);

    const float* kb = g_k + (size_t)nbrj * 256 + h * 32;
    const float* qb = g_q + (size_t)i * 256 + h * 32;
    float dot = 0.f;
#pragma unroll
    for (int d4 = 0; d4 < 4; d4++) {
        float4 kv = *reinterpret_cast<const float4*>(kb + (d4 * 2 + half) * 4);
        float4 qv = *reinterpret_cast<const float4*>(qb + (d4 * 2 + half) * 4);
        dot += qv.x * kv.x + qv.y * kv.y + qv.z * kv.z + qv.w * kv.w;
    }
    dot += __shfl_xor_sync(0xffffffffu, dot, 16);

    float mx = dot;
#pragma unroll
    for (int o = 8; o > 0; o >>= 1) mx = fmaxf(mx, __shfl_xor_sync(0xffffffffu, mx, o));
    float e = __expf(dot - mx);
    float s = e;
#pragma unroll
    for (int o = 8; o > 0; o >>= 1) s += __shfl_xor_sync(0xffffffffu, s, o);
    const float wgt = e / s;

    const float* vb = g_v + h * 32 + lane;
    float acc = 0.f;
#pragma unroll
    for (int j = 0; j < 16; j++) {
        float wj = __shfl_sync(0xffffffffu, wgt, j);
        int   n  = __shfl_sync(0xffffffffu, nj, j);
        acc += wj * vb[(size_t)n * 256];
    }

    __nv_bfloat16 hv = __float2bfloat16(acc);
    const size_t xo = (size_t)i * 256 + h * 32 + lane;
    x_hi[xo] = hv;
    x_lo[xo] = __float2bfloat16(acc - __bfloat162float(hv));
}

// ---------------------------------------------------------------------------
extern "C" void kernel_launch(void* const* d_in, const int* in_sizes, int n_in,
                              void* d_out, int out_size)
{
    const float* feats   = (const float*)d_in[0];
    const int*   index_1 = (const int*)d_in[3];

    int iw = -1;
    for (int i = 0; i < n_in; i++)
        if (in_sizes[i] == 3 * DIMC * DIMC) { iw = i; break; }
    const float* qkv_w  = (const float*)d_in[iw];
    const float* qkv_b  = (const float*)d_in[iw + 1];
    const float* proj_w = (const float*)d_in[iw + 2];
    const float* proj_b = (const float*)d_in[iw + 3];

    const int M = in_sizes[0] / DIMC;   // 50000

    const int SMEM_BYTES = 131072;      // 2 stages x 64KB
    cudaFuncSetAttribute(gemm_mma<1>, cudaFuncAttributeMaxDynamicSharedMemorySize, SMEM_BYTES);
    cudaFuncSetAttribute(gemm_mma<0>, cudaFuncAttributeMaxDynamicSharedMemorySize, SMEM_BYTES);

    cvt_hilo<<<(M * DIMC + 255) / 256, 256>>>(feats, 0, M * DIMC);
    cvt_hilo<<<(768 * 256 + 255) / 256, 256>>>(qkv_w, 1, 768 * 256);
    cvt_hilo<<<(256 * 256 + 255) / 256, 256>>>(proj_w, 2, 256 * 256);

    dim3 g_qkv((M + 127) / 128, 6);     // 768 output cols
    gemm_mma<1><<<g_qkv, 256, SMEM_BYTES>>>(qkv_b, nullptr, M);

    attn_kernel<<<M, 256>>>(index_1, M);

    dim3 g_proj((M + 127) / 128, 2);    // 256 output cols
    gemm_mma<0><<<g_proj, 256, SMEM_BYTES>>>(proj_b, (float*)d_out, M);
}

// round 15
// speedup vs baseline: 1.3164x; 1.2293x over previous
#include <cuda_runtime.h>
#include <cuda_bf16.h>
#include <cstdint>

#define NMAX   50000
#define DIMC   256
#define KNBR   16
#define QSCALE 0.17677669529663689f   // 1/sqrt(32)

// ---------------- device scratch (no allocations allowed) -------------------
__device__ __nv_bfloat16 f_hi[(size_t)NMAX * DIMC];
__device__ __nv_bfloat16 f_lo[(size_t)NMAX * DIMC];
__device__ __nv_bfloat16 w_hi[768 * 256];
__device__ __nv_bfloat16 w_lo[768 * 256];
__device__ __nv_bfloat16 pw_hi[256 * 256];
__device__ __nv_bfloat16 pw_lo[256 * 256];
__device__ float g_q[(size_t)NMAX * DIMC];
__device__ float g_k[(size_t)NMAX * DIMC];
__device__ float g_v[(size_t)NMAX * DIMC];
__device__ __nv_bfloat16 x_hi[(size_t)NMAX * DIMC];
__device__ __nv_bfloat16 x_lo[(size_t)NMAX * DIMC];

// ---------------- helpers ---------------------------------------------------
__device__ __forceinline__ uint32_t smem_u32(const void* p) {
    uint32_t a;
    asm("{ .reg .u64 t; cvta.to.shared.u64 t, %1; cvt.u32.u64 %0, t; }" : "=r"(a) : "l"(p));
    return a;
}
__device__ __forceinline__ void cp_async16(uint32_t saddr, const void* gaddr, int srcb) {
    asm volatile("cp.async.cg.shared.global [%0], [%1], 16, %2;"
                 :: "r"(saddr), "l"(gaddr), "r"(srcb));
}
__device__ __forceinline__ void cp_commit() { asm volatile("cp.async.commit_group;" ::: "memory"); }
__device__ __forceinline__ void cp_wait1()  { asm volatile("cp.async.wait_group 1;" ::: "memory"); }
__device__ __forceinline__ void cp_wait0()  { asm volatile("cp.async.wait_group 0;" ::: "memory"); }

// fp32 -> (bf16 hi, bf16 lo) split.  which: 0=feats, 1=qkv_w, 2=proj_w
__global__ void cvt_hilo(const float* __restrict__ src, int which, int n) {
    int i = blockIdx.x * blockDim.x + threadIdx.x;
    if (i >= n) return;
    __nv_bfloat16* hi = (which == 0) ? f_hi : (which == 1) ? w_hi : pw_hi;
    __nv_bfloat16* lo = (which == 0) ? f_lo : (which == 1) ? w_lo : pw_lo;
    float x = src[i];
    __nv_bfloat16 h = __float2bfloat16(x);
    hi[i] = h;
    lo[i] = __float2bfloat16(x - __bfloat162float(h));
}

// ---------------------------------------------------------------------------
// Fused split-bf16 GEMM on mma.sync, cp.async double-buffered, 512 threads.
// C = A@W^T + bias via AhBh + AhBl + AlBh (fp32 acc, ~16 mantissa bits).
// Block tile 128x128, 16 warps (4x4), warp tile 32x32, K chunks of 64.
// Stage (64KB): AH@0, AL@16K, BH@32K, BL@48K, rows 128B SW-swizzled.
// gmem->smem addressing is done ENTIRELY IN BYTES (R14 bug: element/byte mix).
// SPLIT=1: A=f_hi/lo, W=w_hi/lo (768 cols) -> g_q(*QSCALE)/g_k/g_v
// SPLIT=0: A=x_hi/lo, W=pw_hi/lo (256 cols) -> Cout
// ---------------------------------------------------------------------------
template <int SPLIT>
__global__ void __launch_bounds__(512) gemm_mma(const float* __restrict__ bias,
                                                float* __restrict__ Cout, int M)
{
    extern __shared__ __align__(1024) char smem[];

    const int t    = threadIdx.x;
    const int lane = t & 31;
    const int w    = t >> 5;           // 0..15
    const int wm   = w & 3;            // 4 warps over M (32 rows)
    const int wn   = w >> 2;           // 4 warps over N (32 cols)
    const int m0   = blockIdx.x * 128;
    const int n0   = blockIdx.y * 128;
    const uint32_t sb = smem_u32(smem);

    const __nv_bfloat16* Ah = SPLIT ? f_hi : x_hi;
    const __nv_bfloat16* Al = SPLIT ? f_lo : x_lo;
    const __nv_bfloat16* Bh = SPLIT ? w_hi : pw_hi;
    const __nv_bfloat16* Bl = SPLIT ? w_lo : pw_lo;

    // gmem->smem: thread covers row = t>>2; two 16B chunks at byte offsets
    // cb = (t&3)*16 + j*64 within the row's 128B K-chunk (j = 0,1).
    const int ldRow = t >> 2;
    const int ldQ   = t & 3;
    const bool a_ok  = (m0 + ldRow) < M;
    const int aRow   = a_ok ? (m0 + ldRow) : 0;
    const int aBytes = a_ok ? 16 : 0;
    const uint32_t ldXor = (uint32_t)((ldRow & 7) * 16);

    auto prefetch = [&](int c) {
        const uint32_t stb = sb + (uint32_t)(c & 1) * 65536u;
        // base of this row's 128B chunk (c*64 bf16 = c*128 bytes into the row)
        const char* gAh = (const char*)(Ah + (size_t)aRow * 256 + c * 64);
        const char* gAl = (const char*)(Al + (size_t)aRow * 256 + c * 64);
        const char* gBh = (const char*)(Bh + (size_t)(n0 + ldRow) * 256 + c * 64);
        const char* gBl = (const char*)(Bl + (size_t)(n0 + ldRow) * 256 + c * 64);
#pragma unroll
        for (int j = 0; j < 2; j++) {
            uint32_t cb = (uint32_t)(ldQ * 16 + j * 64);      // byte offset in chunk
            uint32_t so = (uint32_t)(ldRow * 128) + (cb ^ ldXor);
            cp_async16(stb + so,          gAh + cb, aBytes);
            cp_async16(stb + 16384 + so,  gAl + cb, aBytes);
            cp_async16(stb + 32768 + so,  gBh + cb, 16);
            cp_async16(stb + 49152 + so,  gBl + cb, 16);
        }
    };

    // ldmatrix lane address components
    const int aRowIn = lane & 15;
    const int aKbAdd = (lane >> 4) * 16;
    const int bNIn   = (lane & 7) + ((lane >> 4) << 3);
    const int bKbAdd = ((lane >> 3) & 1) * 16;

    float acc[2][4][4];
#pragma unroll
    for (int f = 0; f < 2; f++)
#pragma unroll
        for (int g = 0; g < 4; g++)
#pragma unroll
            for (int e = 0; e < 4; e++) acc[f][g][e] = 0.f;

    prefetch(0);
    cp_commit();

#pragma unroll 1
    for (int c = 0; c < 4; c++) {
        if (c < 3) { prefetch(c + 1); cp_commit(); cp_wait1(); }
        else       { cp_wait0(); }
        __syncthreads();

        const uint32_t stb = sb + (uint32_t)(c & 1) * 65536u;
        const uint32_t bAH = stb, bAL = stb + 16384, bBH = stb + 32768, bBL = stb + 49152;

#pragma unroll
        for (int ks = 0; ks < 4; ks++) {
            const uint32_t kByte = (uint32_t)(ks * 32);

            uint32_t afH[2][4], afL[2][4];
#pragma unroll
            for (int f = 0; f < 2; f++) {
                int row = wm * 32 + f * 16 + aRowIn;
                uint32_t kb  = kByte + (uint32_t)aKbAdd;
                uint32_t off = (uint32_t)(row * 128) + (kb ^ (uint32_t)((row & 7) * 16));
                asm volatile("ldmatrix.sync.aligned.m8n8.x4.shared.b16 {%0,%1,%2,%3}, [%4];"
                             : "=r"(afH[f][0]), "=r"(afH[f][1]), "=r"(afH[f][2]), "=r"(afH[f][3])
                             : "r"(bAH + off));
                asm volatile("ldmatrix.sync.aligned.m8n8.x4.shared.b16 {%0,%1,%2,%3}, [%4];"
                             : "=r"(afL[f][0]), "=r"(afL[f][1]), "=r"(afL[f][2]), "=r"(afL[f][3])
                             : "r"(bAL + off));
            }

            uint32_t bfH[2][4], bfL[2][4];
#pragma unroll
            for (int g2 = 0; g2 < 2; g2++) {
                int nb = wn * 32 + g2 * 16 + bNIn;
                uint32_t kb  = kByte + (uint32_t)bKbAdd;
                uint32_t off = (uint32_t)(nb * 128) + (kb ^ (uint32_t)((nb & 7) * 16));
                asm volatile("ldmatrix.sync.aligned.m8n8.x4.shared.b16 {%0,%1,%2,%3}, [%4];"
                             : "=r"(bfH[g2][0]), "=r"(bfH[g2][1]), "=r"(bfH[g2][2]), "=r"(bfH[g2][3])
                             : "r"(bBH + off));
                asm volatile("ldmatrix.sync.aligned.m8n8.x4.shared.b16 {%0,%1,%2,%3}, [%4];"
                             : "=r"(bfL[g2][0]), "=r"(bfL[g2][1]), "=r"(bfL[g2][2]), "=r"(bfL[g2][3])
                             : "r"(bBL + off));
            }

#define MMA_BF16(ACC, AF, B0, B1)                                              \
            asm volatile(                                                      \
                "mma.sync.aligned.m16n8k16.row.col.f32.bf16.bf16.f32 "        \
                "{%0,%1,%2,%3}, {%4,%5,%6,%7}, {%8,%9}, {%0,%1,%2,%3};"       \
                : "+f"((ACC)[0]), "+f"((ACC)[1]), "+f"((ACC)[2]), "+f"((ACC)[3]) \
                : "r"((AF)[0]), "r"((AF)[1]), "r"((AF)[2]), "r"((AF)[3]),      \
                  "r"(B0), "r"(B1))

#pragma unroll
            for (int f = 0; f < 2; f++)
#pragma unroll
                for (int g2 = 0; g2 < 2; g2++) {
                    MMA_BF16(acc[f][g2 * 2],     afH[f], bfH[g2][0], bfH[g2][1]);
                    MMA_BF16(acc[f][g2 * 2 + 1], afH[f], bfH[g2][2], bfH[g2][3]);
                    MMA_BF16(acc[f][g2 * 2],     afH[f], bfL[g2][0], bfL[g2][1]);
                    MMA_BF16(acc[f][g2 * 2 + 1], afH[f], bfL[g2][2], bfL[g2][3]);
                    MMA_BF16(acc[f][g2 * 2],     afL[f], bfH[g2][0], bfH[g2][1]);
                    MMA_BF16(acc[f][g2 * 2 + 1], afL[f], bfH[g2][2], bfH[g2][3]);
                }
#undef MMA_BF16
        }
        if (c < 3) __syncthreads();
    }

    // ---- epilogue ----
    const int rBase = m0 + wm * 32 + (lane >> 2);
    const int cIn   = (lane & 3) * 2;

    const int sect = SPLIT ? (n0 >> 8) : 0;
    float* dstBase = SPLIT ? ((sect == 0) ? g_q : (sect == 1) ? g_k : g_v) : Cout;
    const float mult = (SPLIT && sect == 0) ? QSCALE : 1.0f;
    const int nLocal = SPLIT ? (n0 & 255) : n0;

#pragma unroll
    for (int f = 0; f < 2; f++) {
#pragma unroll
        for (int g = 0; g < 4; g++) {
            const int colFull = n0 + wn * 32 + g * 8 + cIn;
            const int colOut  = nLocal + wn * 32 + g * 8 + cIn;
            const float b0 = bias[colFull], b1 = bias[colFull + 1];
#pragma unroll
            for (int h = 0; h < 2; h++) {
                const int row = rBase + f * 16 + h * 8;
                if (row < M) {
                    float2 ov;
                    ov.x = (acc[f][g][h * 2 + 0] + b0) * mult;
                    ov.y = (acc[f][g][h * 2 + 1] + b1) * mult;
                    *reinterpret_cast<float2*>(dstBase + (size_t)row * 256 + colOut) = ov;
                }
            }
        }
    }
}

// ---------------------------------------------------------------------------
// Attention: block per point (256 threads, 8 warps = 8 heads).
// Full 16 k-rows (16KB) staged ONCE per block with dense coalesced LDGs
// (each 128B line fetched exactly once); 16B chunks XOR-swizzled by row so
// per-head LDS reads run conflict-free. V stays direct (1 line per LDG).
// ---------------------------------------------------------------------------
__global__ void __launch_bounds__(256) attn_kernel(const int* __restrict__ index_1, int M)
{
    __shared__ __align__(16) float ks[16 * 256];   // 16KB: 16 rows x 1KB
    const int i    = blockIdx.x;                   // grid.x == M
    const int t    = threadIdx.x;
    const int h    = t >> 5;                       // warp = head
    const int lane = t & 31;

    // ---- stage k rows: thread t owns row j=t>>4, 16B chunks c = it*16+(t&15)
    {
        const int j  = t >> 4;
        const int jr = __ldg(index_1 + i * KNBR + j);
        const float* src = g_k + (size_t)jr * 256;
        const int cl = t & 15;
#pragma unroll
        for (int it = 0; it < 4; it++) {
            int c  = it * 16 + cl;
            int cs = c ^ (j & 7);                  // swizzled chunk
            float4 v4 = *reinterpret_cast<const float4*>(src + c * 4);
            *reinterpret_cast<float4*>(reinterpret_cast<char*>(ks) + j * 1024 + cs * 16) = v4;
        }
    }

    int nj = 0;
    if (lane < 16) nj = __ldg(index_1 + i * KNBR + lane);
    __syncthreads();

    // ---- logits from smem k + gmem q (L1-broadcast) ----
    const int jj   = lane & 15;
    const int half = lane >> 4;
    const float* qb = g_q + (size_t)i * 256 + h * 32;

    float dot = 0.f;
#pragma unroll
    for (int d4 = 0; d4 < 4; d4++) {
        int c  = h * 8 + 2 * d4 + half;
        int cs = c ^ (jj & 7);
        float4 kv = *reinterpret_cast<const float4*>(reinterpret_cast<char*>(ks) + jj * 1024 + cs * 16);
        float4 qv = *reinterpret_cast<const float4*>(qb + (2 * d4 + half) * 4);
        dot += qv.x * kv.x + qv.y * kv.y + qv.z * kv.z + qv.w * kv.w;
    }
    dot += __shfl_xor_sync(0xffffffffu, dot, 16);

    float mx = dot;
#pragma unroll
    for (int o = 8; o > 0; o >>= 1) mx = fmaxf(mx, __shfl_xor_sync(0xffffffffu, mx, o));
    float e = __expf(dot - mx);
    float s = e;
#pragma unroll
    for (int o = 8; o > 0; o >>= 1) s += __shfl_xor_sync(0xffffffffu, s, o);
    const float wgt = e / s;

    // ---- weighted V: lane = dim, direct gmem (coalesced 128B per neighbor) ----
    const float* vb = g_v + h * 32 + lane;
    float acc = 0.f;
#pragma unroll
    for (int j = 0; j < 16; j++) {
        float wj = __shfl_sync(0xffffffffu, wgt, j);
        int   n  = __shfl_sync(0xffffffffu, nj, j);
        acc += wj * vb[(size_t)n * 256];
    }

    __nv_bfloat16 hv = __float2bfloat16(acc);
    const size_t xo = (size_t)i * 256 + h * 32 + lane;
    x_hi[xo] = hv;
    x_lo[xo] = __float2bfloat16(acc - __bfloat162float(hv));
}

// ---------------------------------------------------------------------------
extern "C" void kernel_launch(void* const* d_in, const int* in_sizes, int n_in,
                              void* d_out, int out_size)
{
    const float* feats   = (const float*)d_in[0];
    const int*   index_1 = (const int*)d_in[3];

    int iw = -1;
    for (int i = 0; i < n_in; i++)
        if (in_sizes[i] == 3 * DIMC * DIMC) { iw = i; break; }
    const float* qkv_w  = (const float*)d_in[iw];
    const float* qkv_b  = (const float*)d_in[iw + 1];
    const float* proj_w = (const float*)d_in[iw + 2];
    const float* proj_b = (const float*)d_in[iw + 3];

    const int M = in_sizes[0] / DIMC;   // 50000

    const int SMEM_BYTES = 131072;      // 2 stages x 64KB
    cudaFuncSetAttribute(gemm_mma<1>, cudaFuncAttributeMaxDynamicSharedMemorySize, SMEM_BYTES);
    cudaFuncSetAttribute(gemm_mma<0>, cudaFuncAttributeMaxDynamicSharedMemorySize, SMEM_BYTES);

    cvt_hilo<<<(M * DIMC + 255) / 256, 256>>>(feats, 0, M * DIMC);
    cvt_hilo<<<(768 * 256 + 255) / 256, 256>>>(qkv_w, 1, 768 * 256);
    cvt_hilo<<<(256 * 256 + 255) / 256, 256>>>(proj_w, 2, 256 * 256);

    dim3 g_qkv((M + 127) / 128, 6);     // 768 output cols
    gemm_mma<1><<<g_qkv, 512, SMEM_BYTES>>>(qkv_b, nullptr, M);

    attn_kernel<<<M, 256>>>(index_1, M);

    dim3 g_proj((M + 127) / 128, 2);    // 256 output cols
    gemm_mma<0><<<g_proj, 512, SMEM_BYTES>>>(proj_b, (float*)d_out, M);
}

// round 16
// speedup vs baseline: 1.3179x; 1.0011x over previous
#include <cuda_runtime.h>
#include <cuda_bf16.h>
#include <cstdint>

#define NMAX   50000
#define DIMC   256
#define KNBR   16
#define QSCALE 0.17677669529663689f   // 1/sqrt(32)

// ---------------- device scratch (no allocations allowed) -------------------
__device__ __nv_bfloat16 f_hi[(size_t)NMAX * DIMC];
__device__ __nv_bfloat16 f_lo[(size_t)NMAX * DIMC];
__device__ __nv_bfloat16 w_hi[768 * 256];
__device__ __nv_bfloat16 w_lo[768 * 256];
__device__ __nv_bfloat16 pw_hi[256 * 256];
__device__ __nv_bfloat16 pw_lo[256 * 256];
__device__ float g_q[(size_t)NMAX * DIMC];
__device__ float g_k[(size_t)NMAX * DIMC];
__device__ float g_v[(size_t)NMAX * DIMC];
__device__ __nv_bfloat16 x_hi[(size_t)NMAX * DIMC];
__device__ __nv_bfloat16 x_lo[(size_t)NMAX * DIMC];

// ---------------- helpers ---------------------------------------------------
__device__ __forceinline__ uint32_t smem_u32(const void* p) {
    uint32_t a;
    asm("{ .reg .u64 t; cvta.to.shared.u64 t, %1; cvt.u32.u64 %0, t; }" : "=r"(a) : "l"(p));
    return a;
}
__device__ __forceinline__ void cp_async16(uint32_t saddr, const void* gaddr, int srcb) {
    asm volatile("cp.async.cg.shared.global [%0], [%1], 16, %2;"
                 :: "r"(saddr), "l"(gaddr), "r"(srcb));
}
__device__ __forceinline__ void cp_commit() { asm volatile("cp.async.commit_group;" ::: "memory"); }
__device__ __forceinline__ void cp_wait1()  { asm volatile("cp.async.wait_group 1;" ::: "memory"); }
__device__ __forceinline__ void cp_wait0()  { asm volatile("cp.async.wait_group 0;" ::: "memory"); }

// fp32 -> (bf16 hi, bf16 lo) split.  which: 0=feats, 1=qkv_w, 2=proj_w
__global__ void cvt_hilo(const float* __restrict__ src, int which, int n) {
    int i = blockIdx.x * blockDim.x + threadIdx.x;
    if (i >= n) return;
    __nv_bfloat16* hi = (which == 0) ? f_hi : (which == 1) ? w_hi : pw_hi;
    __nv_bfloat16* lo = (which == 0) ? f_lo : (which == 1) ? w_lo : pw_lo;
    float x = src[i];
    __nv_bfloat16 h = __float2bfloat16(x);
    hi[i] = h;
    lo[i] = __float2bfloat16(x - __bfloat162float(h));
}

// ---------------------------------------------------------------------------
// Fused split-bf16 GEMM on mma.sync, cp.async double-buffered, 512 threads.
// C = A@W^T + bias via AhBh + AhBl + AlBh (fp32 acc, ~16 mantissa bits).
// Block tile 128x256, 16 warps (4x4), warp tile 32x64, K chunks of 64.
// Stage (96KB): AH@0(16K), AL@16K, BH@32K(32K), BL@64K(32K); 2 stages=192KB.
// Per k-step: 12 ldmatrix -> 48 MMAs (ratio 4.0 vs 1.5 at 32x32 warp tile).
// N-tiles are 256-aligned so each SPLIT=1 tile is exactly one of q/k/v.
// SPLIT=1: A=f_hi/lo, W=w_hi/lo (768 cols, grid.y=3) -> g_q(*QSCALE)/g_k/g_v
// SPLIT=0: A=x_hi/lo, W=pw_hi/lo (256 cols, grid.y=1) -> Cout
// ---------------------------------------------------------------------------
template <int SPLIT>
__global__ void __launch_bounds__(512) gemm_mma(const float* __restrict__ bias,
                                                float* __restrict__ Cout, int M)
{
    extern __shared__ __align__(1024) char smem[];

    const int t    = threadIdx.x;
    const int lane = t & 31;
    const int w    = t >> 5;           // 0..15
    const int wm   = w & 3;            // 4 warps over M (32 rows)
    const int wn   = w >> 2;           // 4 warps over N (64 cols)
    const int m0   = blockIdx.x * 128;
    const int n0   = blockIdx.y * 256;
    const uint32_t sb = smem_u32(smem);

    const __nv_bfloat16* Ah = SPLIT ? f_hi : x_hi;
    const __nv_bfloat16* Al = SPLIT ? f_lo : x_lo;
    const __nv_bfloat16* Bh = SPLIT ? w_hi : pw_hi;
    const __nv_bfloat16* Bl = SPLIT ? w_lo : pw_lo;

    // A loader: thread t covers row t>>2 (128 rows); byte chunks cb = (t&3)*16 + j*64
    const int aRowL = t >> 2;
    const int aQ    = t & 3;
    const bool a_ok  = (m0 + aRowL) < M;
    const int aRow   = a_ok ? (m0 + aRowL) : 0;
    const int aBytes = a_ok ? 16 : 0;
    const uint32_t aXor = (uint32_t)((aRowL & 7) * 16);

    // B loader: thread t covers row t>>1 (256 rows); byte chunks cb = (t&1)*64 + j*16
    const int bRowL = t >> 1;
    const int bHalf = t & 1;
    const uint32_t bXor = (uint32_t)((bRowL & 7) * 16);

    auto prefetch = [&](int c) {
        const uint32_t stb = sb + (uint32_t)(c & 1) * 98304u;
        const char* gAh = (const char*)(Ah + (size_t)aRow * 256 + c * 64);
        const char* gAl = (const char*)(Al + (size_t)aRow * 256 + c * 64);
#pragma unroll
        for (int j = 0; j < 2; j++) {
            uint32_t cb = (uint32_t)(aQ * 16 + j * 64);
            uint32_t so = (uint32_t)(aRowL * 128) + (cb ^ aXor);
            cp_async16(stb + so,         gAh + cb, aBytes);
            cp_async16(stb + 16384 + so, gAl + cb, aBytes);
        }
        const char* gBh = (const char*)(Bh + (size_t)(n0 + bRowL) * 256 + c * 64);
        const char* gBl = (const char*)(Bl + (size_t)(n0 + bRowL) * 256 + c * 64);
#pragma unroll
        for (int j = 0; j < 4; j++) {
            uint32_t cb = (uint32_t)(bHalf * 64 + j * 16);
            uint32_t so = (uint32_t)(bRowL * 128) + (cb ^ bXor);
            cp_async16(stb + 32768 + so, gBh + cb, 16);
            cp_async16(stb + 65536 + so, gBl + cb, 16);
        }
    };

    // ldmatrix lane address components
    const int aRowIn = lane & 15;
    const int aKbAdd = (lane >> 4) * 16;
    const int bNIn   = (lane & 7) + ((lane >> 4) << 3);
    const int bKbAdd = ((lane >> 3) & 1) * 16;

    float acc[2][8][4];
#pragma unroll
    for (int f = 0; f < 2; f++)
#pragma unroll
        for (int g = 0; g < 8; g++)
#pragma unroll
            for (int e = 0; e < 4; e++) acc[f][g][e] = 0.f;

    prefetch(0);
    cp_commit();

#pragma unroll 1
    for (int c = 0; c < 4; c++) {
        if (c < 3) { prefetch(c + 1); cp_commit(); cp_wait1(); }
        else       { cp_wait0(); }
        __syncthreads();

        const uint32_t stb = sb + (uint32_t)(c & 1) * 98304u;
        const uint32_t bAH = stb, bAL = stb + 16384, bBH = stb + 32768, bBL = stb + 65536;

#pragma unroll
        for (int ks = 0; ks < 4; ks++) {
            const uint32_t kByte = (uint32_t)(ks * 32);

            uint32_t afH[2][4], afL[2][4];
#pragma unroll
            for (int f = 0; f < 2; f++) {
                int row = wm * 32 + f * 16 + aRowIn;
                uint32_t kb  = kByte + (uint32_t)aKbAdd;
                uint32_t off = (uint32_t)(row * 128) + (kb ^ (uint32_t)((row & 7) * 16));
                asm volatile("ldmatrix.sync.aligned.m8n8.x4.shared.b16 {%0,%1,%2,%3}, [%4];"
                             : "=r"(afH[f][0]), "=r"(afH[f][1]), "=r"(afH[f][2]), "=r"(afH[f][3])
                             : "r"(bAH + off));
                asm volatile("ldmatrix.sync.aligned.m8n8.x4.shared.b16 {%0,%1,%2,%3}, [%4];"
                             : "=r"(afL[f][0]), "=r"(afL[f][1]), "=r"(afL[f][2]), "=r"(afL[f][3])
                             : "r"(bAL + off));
            }

#define MMA_BF16(ACC, AF, B0, B1)                                              \
            asm volatile(                                                      \
                "mma.sync.aligned.m16n8k16.row.col.f32.bf16.bf16.f32 "        \
                "{%0,%1,%2,%3}, {%4,%5,%6,%7}, {%8,%9}, {%0,%1,%2,%3};"       \
                : "+f"((ACC)[0]), "+f"((ACC)[1]), "+f"((ACC)[2]), "+f"((ACC)[3]) \
                : "r"((AF)[0]), "r"((AF)[1]), "r"((AF)[2]), "r"((AF)[3]),      \
                  "r"(B0), "r"(B1))

            // B fragments loaded per 16-col group to bound register pressure
#pragma unroll
            for (int g2 = 0; g2 < 4; g2++) {
                int nb = wn * 64 + g2 * 16 + bNIn;
                uint32_t kb  = kByte + (uint32_t)bKbAdd;
                uint32_t off = (uint32_t)(nb * 128) + (kb ^ (uint32_t)((nb & 7) * 16));
                uint32_t bh[4], bl[4];
                asm volatile("ldmatrix.sync.aligned.m8n8.x4.shared.b16 {%0,%1,%2,%3}, [%4];"
                             : "=r"(bh[0]), "=r"(bh[1]), "=r"(bh[2]), "=r"(bh[3])
                             : "r"(bBH + off));
                asm volatile("ldmatrix.sync.aligned.m8n8.x4.shared.b16 {%0,%1,%2,%3}, [%4];"
                             : "=r"(bl[0]), "=r"(bl[1]), "=r"(bl[2]), "=r"(bl[3])
                             : "r"(bBL + off));
#pragma unroll
                for (int f = 0; f < 2; f++) {
                    MMA_BF16(acc[f][g2 * 2],     afH[f], bh[0], bh[1]);
                    MMA_BF16(acc[f][g2 * 2 + 1], afH[f], bh[2], bh[3]);
                    MMA_BF16(acc[f][g2 * 2],     afH[f], bl[0], bl[1]);
                    MMA_BF16(acc[f][g2 * 2 + 1], afH[f], bl[2], bl[3]);
                    MMA_BF16(acc[f][g2 * 2],     afL[f], bh[0], bh[1]);
                    MMA_BF16(acc[f][g2 * 2 + 1], afL[f], bh[2], bh[3]);
                }
            }
#undef MMA_BF16
        }
        if (c < 3) __syncthreads();
    }

    // ---- epilogue ----
    const int rBase = m0 + wm * 32 + (lane >> 2);
    const int cIn   = (lane & 3) * 2;

    const int sect = SPLIT ? (n0 >> 8) : 0;     // 256-aligned tile => one section
    float* dstBase = SPLIT ? ((sect == 0) ? g_q : (sect == 1) ? g_k : g_v) : Cout;
    const float mult = (SPLIT && sect == 0) ? QSCALE : 1.0f;
    const int nLocal = SPLIT ? 0 : n0;          // column within section

#pragma unroll
    for (int f = 0; f < 2; f++) {
#pragma unroll
        for (int g = 0; g < 8; g++) {
            const int colFull = n0 + wn * 64 + g * 8 + cIn;
            const int colOut  = nLocal + wn * 64 + g * 8 + cIn;
            const float b0 = bias[colFull], b1 = bias[colFull + 1];
#pragma unroll
            for (int h = 0; h < 2; h++) {
                const int row = rBase + f * 16 + h * 8;
                if (row < M) {
                    float2 ov;
                    ov.x = (acc[f][g][h * 2 + 0] + b0) * mult;
                    ov.y = (acc[f][g][h * 2 + 1] + b1) * mult;
                    *reinterpret_cast<float2*>(dstBase + (size_t)row * 256 + colOut) = ov;
                }
            }
        }
    }
}

// ---------------------------------------------------------------------------
// Attention: block per point (256 threads, 8 warps = 8 heads).
// Full 16 k-rows (16KB) staged once per block with dense coalesced LDGs;
// 16B chunks XOR-swizzled by row for conflict-free LDS. V direct.
// ---------------------------------------------------------------------------
__global__ void __launch_bounds__(256) attn_kernel(const int* __restrict__ index_1, int M)
{
    __shared__ __align__(16) float ks[16 * 256];   // 16KB: 16 rows x 1KB
    const int i    = blockIdx.x;                   // grid.x == M
    const int t    = threadIdx.x;
    const int h    = t >> 5;                       // warp = head
    const int lane = t & 31;

    {
        const int j  = t >> 4;
        const int jr = __ldg(index_1 + i * KNBR + j);
        const float* src = g_k + (size_t)jr * 256;
        const int cl = t & 15;
#pragma unroll
        for (int it = 0; it < 4; it++) {
            int c  = it * 16 + cl;
            int cs = c ^ (j & 7);
            float4 v4 = *reinterpret_cast<const float4*>(src + c * 4);
            *reinterpret_cast<float4*>(reinterpret_cast<char*>(ks) + j * 1024 + cs * 16) = v4;
        }
    }

    int nj = 0;
    if (lane < 16) nj = __ldg(index_1 + i * KNBR + lane);
    __syncthreads();

    const int jj   = lane & 15;
    const int half = lane >> 4;
    const float* qb = g_q + (size_t)i * 256 + h * 32;

    float dot = 0.f;
#pragma unroll
    for (int d4 = 0; d4 < 4; d4++) {
        int c  = h * 8 + 2 * d4 + half;
        int cs = c ^ (jj & 7);
        float4 kv = *reinterpret_cast<const float4*>(reinterpret_cast<char*>(ks) + jj * 1024 + cs * 16);
        float4 qv = *reinterpret_cast<const float4*>(qb + (2 * d4 + half) * 4);
        dot += qv.x * kv.x + qv.y * kv.y + qv.z * kv.z + qv.w * kv.w;
    }
    dot += __shfl_xor_sync(0xffffffffu, dot, 16);

    float mx = dot;
#pragma unroll
    for (int o = 8; o > 0; o >>= 1) mx = fmaxf(mx, __shfl_xor_sync(0xffffffffu, mx, o));
    float e = __expf(dot - mx);
    float s = e;
#pragma unroll
    for (int o = 8; o > 0; o >>= 1) s += __shfl_xor_sync(0xffffffffu, s, o);
    const float wgt = e / s;

    const float* vb = g_v + h * 32 + lane;
    float acc = 0.f;
#pragma unroll
    for (int j = 0; j < 16; j++) {
        float wj = __shfl_sync(0xffffffffu, wgt, j);
        int   n  = __shfl_sync(0xffffffffu, nj, j);
        acc += wj * vb[(size_t)n * 256];
    }

    __nv_bfloat16 hv = __float2bfloat16(acc);
    const size_t xo = (size_t)i * 256 + h * 32 + lane;
    x_hi[xo] = hv;
    x_lo[xo] = __float2bfloat16(acc - __bfloat162float(hv));
}

// ---------------------------------------------------------------------------
extern "C" void kernel_launch(void* const* d_in, const int* in_sizes, int n_in,
                              void* d_out, int out_size)
{
    const float* feats   = (const float*)d_in[0];
    const int*   index_1 = (const int*)d_in[3];

    int iw = -1;
    for (int i = 0; i < n_in; i++)
        if (in_sizes[i] == 3 * DIMC * DIMC) { iw = i; break; }
    const float* qkv_w  = (const float*)d_in[iw];
    const float* qkv_b  = (const float*)d_in[iw + 1];
    const float* proj_w = (const float*)d_in[iw + 2];
    const float* proj_b = (const float*)d_in[iw + 3];

    const int M = in_sizes[0] / DIMC;   // 50000

    const int SMEM_BYTES = 196608;      // 2 stages x 96KB
    cudaFuncSetAttribute(gemm_mma<1>, cudaFuncAttributeMaxDynamicSharedMemorySize, SMEM_BYTES);
    cudaFuncSetAttribute(gemm_mma<0>, cudaFuncAttributeMaxDynamicSharedMemorySize, SMEM_BYTES);

    cvt_hilo<<<(M * DIMC + 255) / 256, 256>>>(feats, 0, M * DIMC);
    cvt_hilo<<<(768 * 256 + 255) / 256, 256>>>(qkv_w, 1, 768 * 256);
    cvt_hilo<<<(256 * 256 + 255) / 256, 256>>>(proj_w, 2, 256 * 256);

    dim3 g_qkv((M + 127) / 128, 3);     // 768 output cols, N-tile 256
    gemm_mma<1><<<g_qkv, 512, SMEM_BYTES>>>(qkv_b, nullptr, M);

    attn_kernel<<<M, 256>>>(index_1, M);

    dim3 g_proj((M + 127) / 128, 1);    // 256 output cols
    gemm_mma<0><<<g_proj, 512, SMEM_BYTES>>>(proj_b, (float*)d_out, M);
}